// round 3
// baseline (speedup 1.0000x reference)
#include <cuda_runtime.h>

#define N_NODES 20000
#define F_DIM   4
#define T_DIM   12
#define C_DIM   256
#define FT      48          // F*T
#define ER_E    30000
#define HID_D   128
#define OUT_D   12
#define NREG    5

// ---------------- device scratch (no allocations allowed) ----------------
__device__ float g_dinv[NREG * N_NODES];   // deg, converted to rsqrt(deg) in place
__device__ float g_selfc[N_NODES];         // sum_r 1/deg_r
__device__ float g_AX[N_NODES * FT];       // aggregated x, layout [n][t*4+f]
__device__ float g_Mz[F_DIM * C_DIM];
__device__ float g_Mh[F_DIM * C_DIM];
__device__ float g_bz[C_DIM];
__device__ float g_bh[C_DIM];
__device__ float g_probs[T_DIM];
__device__ float g_hreluT[C_DIM * N_NODES];  // relu(h), TRANSPOSED [c][n]

struct RegPtrs { const int* idx[NREG]; const float* w[NREG]; };

// ---------------- small kernels ----------------
__global__ void k_init_deg() {
    int i = blockIdx.x * blockDim.x + threadIdx.x;
    if (i < NREG * N_NODES) g_dinv[i] = 1.0f;   // self-loop contributes 1
}

__global__ void k_deg(RegPtrs rp) {
    int e = blockIdx.x * blockDim.x + threadIdx.x;
    int r = blockIdx.y;
    if (e < ER_E) {
        int dst = rp.idx[r][ER_E + e];
        atomicAdd(&g_dinv[r * N_NODES + dst], rp.w[r][e]);
    }
}

__global__ void k_dinv() {
    int i = blockIdx.x * blockDim.x + threadIdx.x;
    if (i < N_NODES) {
        float s = 0.f;
#pragma unroll
        for (int r = 0; r < NREG; r++) {
            float d = g_dinv[r * N_NODES + i];
            g_dinv[r * N_NODES + i] = rsqrtf(d);
            s += __fdividef(1.0f, d);
        }
        g_selfc[i] = s;
    }
}

// self-loop term, with [f][t] -> [t*4+f] relayout
__global__ void k_ax_self(const float* __restrict__ x) {
    int i = blockIdx.x * blockDim.x + threadIdx.x;
    if (i < N_NODES * FT) {
        int n = i / FT;
        int e = i - n * FT;          // e = f*12 + t in source layout
        int f = e / T_DIM;
        int t = e - f * T_DIM;
        g_AX[n * FT + t * 4 + f] = g_selfc[n] * x[i];
    }
}

// one warp per edge: gather 48 floats from x[src], atomicAdd into AX[dst] ([t*4+f] layout)
__global__ void k_scatter(RegPtrs rp, const float* __restrict__ x) {
    int warp = (blockIdx.x * blockDim.x + threadIdx.x) >> 5;
    int lane = threadIdx.x & 31;
    int r = blockIdx.y;
    if (warp >= ER_E) return;
    const int* idx = rp.idx[r];
    int src = idx[warp];
    int dst = idx[ER_E + warp];
    float coef = g_dinv[r * N_NODES + src] * rp.w[r][warp] * g_dinv[r * N_NODES + dst];
    const float* xs = x + (size_t)src * FT;
    float* ax = g_AX + (size_t)dst * FT;
    int e = lane, f = e / T_DIM, t = e - f * T_DIM;
    atomicAdd(&ax[t * 4 + f], coef * xs[e]);
    if (lane < 16) {
        e = 32 + lane; f = e / T_DIM; t = e - f * T_DIM;
        atomicAdd(&ax[t * 4 + f], coef * xs[e]);
    }
}

// M = Wc @ Wl[:C], b' = bc @ Wl[:C] + bl  (both gates); softmax(attention)
__global__ void k_precompute(const float* __restrict__ Wc_z, const float* __restrict__ bc_z,
                             const float* __restrict__ Wl_z, const float* __restrict__ bl_z,
                             const float* __restrict__ Wc_h, const float* __restrict__ bc_h,
                             const float* __restrict__ Wl_h, const float* __restrict__ bl_h,
                             const float* __restrict__ attention) {
    __shared__ float sWcz[F_DIM * C_DIM], sWch[F_DIM * C_DIM];
    __shared__ float sbcz[C_DIM], sbch[C_DIM];
    int tid = threadIdx.x;  // 256 threads
    for (int i = tid; i < F_DIM * C_DIM; i += 256) { sWcz[i] = Wc_z[i]; sWch[i] = Wc_h[i]; }
    sbcz[tid] = bc_z[tid];
    sbch[tid] = bc_h[tid];
    __syncthreads();
    float mz[F_DIM] = {0, 0, 0, 0}, mh[F_DIM] = {0, 0, 0, 0}, bz = 0.f, bh = 0.f;
    for (int k = 0; k < C_DIM; k++) {
        float wz = Wl_z[k * C_DIM + tid];
        float wh = Wl_h[k * C_DIM + tid];
#pragma unroll
        for (int f = 0; f < F_DIM; f++) {
            mz[f] = fmaf(sWcz[f * C_DIM + k], wz, mz[f]);
            mh[f] = fmaf(sWch[f * C_DIM + k], wh, mh[f]);
        }
        bz = fmaf(sbcz[k], wz, bz);
        bh = fmaf(sbch[k], wh, bh);
    }
#pragma unroll
    for (int f = 0; f < F_DIM; f++) {
        g_Mz[f * C_DIM + tid] = mz[f];
        g_Mh[f * C_DIM + tid] = mh[f];
    }
    g_bz[tid] = bz + bl_z[tid];
    g_bh[tid] = bh + bl_h[tid];
    if (tid == 0) {
        float mx = -1e30f;
        for (int t = 0; t < T_DIM; t++) mx = fmaxf(mx, attention[t]);
        float p[T_DIM], s = 0.f;
        for (int t = 0; t < T_DIM; t++) { p[t] = __expf(attention[t] - mx); s += p[t]; }
        float is = __fdividef(1.0f, s);
        for (int t = 0; t < T_DIM; t++) g_probs[t] = p[t] * is;
    }
}

// ---------------- gate kernel: gates + attention pooling -> h ----------------
// smem (floats): Mz 1024 | Mh 1024 | bz 256 | bh 256 | AX 32*48=1536 | hs 32*257=8224
#define GATE_NPB   32
#define GATE_SMEMF (1024 + 1024 + 256 + 256 + 1536 + 32 * 257)
#define GATE_SMEMB (GATE_SMEMF * 4)

__global__ void __launch_bounds__(256, 4)
k_gate(float* __restrict__ out_h, int write_h) {
    extern __shared__ float sm[];
    float* Mzs = sm;                 // 1024
    float* Mhs = Mzs + 1024;         // 1024
    float* bzs = Mhs + 1024;         // 256
    float* bhs = bzs + 256;          // 256
    float* AXs = bhs + 256;          // 1536, layout [n][t*4+f]
    float* hs  = AXs + 1536;         // 32 * 257 (padded for transpose)

    int tid = threadIdx.x;
    for (int i = tid; i < 1024; i += 256) { Mzs[i] = g_Mz[i]; Mhs[i] = g_Mh[i]; }
    bzs[tid] = g_bz[tid];
    bhs[tid] = g_bh[tid];
    int base = blockIdx.x * GATE_NPB;
    for (int i = tid; i < GATE_NPB * FT; i += 256) AXs[i] = g_AX[base * FT + i];
    __syncthreads();

    float pr[T_DIM];
#pragma unroll
    for (int t = 0; t < T_DIM; t++) pr[t] = g_probs[t];

    int c = tid;
    float mz0 = Mzs[c], mz1 = Mzs[256 + c], mz2 = Mzs[512 + c], mz3 = Mzs[768 + c];
    float mh0 = Mhs[c], mh1 = Mhs[256 + c], mh2 = Mhs[512 + c], mh3 = Mhs[768 + c];
    float bz = bzs[c], bh = bhs[c];
    for (int ln = 0; ln < GATE_NPB; ln++) {
        const float4* ax4 = (const float4*)(AXs + ln * FT);
        float acc = 0.f;
#pragma unroll
        for (int t = 0; t < T_DIM; t++) {
            float4 a = ax4[t];
            float az = fmaf(a.w, mz3, fmaf(a.z, mz2, fmaf(a.y, mz1, fmaf(a.x, mz0, bz))));
            float ah = fmaf(a.w, mh3, fmaf(a.z, mh2, fmaf(a.y, mh1, fmaf(a.x, mh0, bh))));
            // (1-sigmoid(az))*tanh(ah) = (e2-1) / ((1+ez)*(e2+1)),  e2=e^{2ah}, ez=e^{az}
            float ez  = __expf(az);
            float e2  = __expf(fminf(ah, 44.0f) * 2.0f);   // keep num finite; den=inf -> val=0 (correct limit)
            float num = e2 - 1.0f;
            float den = (1.0f + ez) * (e2 + 1.0f);
            acc = fmaf(pr[t], __fdividef(num, den), acc);
        }
        if (write_h) out_h[(base + ln) * C_DIM + c] = acc;   // raw h output
        hs[ln * 257 + c] = fmaxf(acc, 0.f);
    }
    __syncthreads();

    // transposed, relu'd write: g_hreluT[c][n] (coalesced over n, conflict-free smem reads)
    for (int idx = tid; idx < GATE_NPB * C_DIM; idx += 256) {
        int cc = idx >> 5, n = idx & 31;
        g_hreluT[cc * N_NODES + base + n] = hs[n * 257 + cc];
    }
}

// ---------------- MLP kernel: relu(h) @ W1 -> relu -> @ W2 ----------------
// smem (floats): W1s 32768 | hTs 16384 (reused as y1s) | b1 128 | b2 16 | W2 1536
#define MLP_NPB   64
#define MLP_SMEMF (32768 + 16384 + 128 + 16 + 1536)
#define MLP_SMEMB (MLP_SMEMF * 4)

__global__ void __launch_bounds__(256, 1)
k_mlp(const float* __restrict__ W1, const float* __restrict__ b1,
      const float* __restrict__ W2, const float* __restrict__ b2,
      float* __restrict__ out_y) {
    extern __shared__ float sm[];
    float* W1s = sm;                  // 32768  [k][j]
    float* hTs = W1s + 32768;         // 16384  [k][n]  (aliased to y1s after sync)
    float* b1s = hTs + 16384;         // 128
    float* b2s = b1s + 128;           // 16
    float* W2s = b2s + 16;            // 1536

    int tid = threadIdx.x;
    int base = blockIdx.x * MLP_NPB;

    {
        float4* d4 = (float4*)W1s;
        const float4* s4 = (const float4*)W1;
        for (int i = tid; i < 32768 / 4; i += 256) d4[i] = s4[i];
    }
    for (int i = tid; i < 1536; i += 256) W2s[i] = W2[i];
    if (tid < HID_D) b1s[tid] = b1[tid];
    if (tid < 16) b2s[tid] = (tid < OUT_D) ? b2[tid] : 0.f;
    for (int i = tid; i < C_DIM * MLP_NPB; i += 256) {
        int k = i >> 6, n = i & 63;
        int gn = base + n;
        hTs[i] = (gn < N_NODES) ? g_hreluT[k * N_NODES + gn] : 0.f;
    }
    __syncthreads();

    // layer 1 on the packed-fp32 pipe: thread (j, half) does 32 nodes = 16 f32x2 pairs
    int j = tid & 127;
    int half = tid >> 7;
    unsigned long long acc[16];
    {
        float bj = b1s[j];
        unsigned long long binit;
        asm("mov.b64 %0, {%1,%1};" : "=l"(binit) : "f"(bj));
#pragma unroll
        for (int p = 0; p < 16; p++) acc[p] = binit;
    }
    const float* hbase = hTs + half * 32;
#pragma unroll 2
    for (int k = 0; k < C_DIM; k++) {
        float w = W1s[k * HID_D + j];
        unsigned long long w2;
        asm("mov.b64 %0, {%1,%1};" : "=l"(w2) : "f"(w));
        const ulonglong2* hp = (const ulonglong2*)(hbase + k * MLP_NPB);
#pragma unroll
        for (int q = 0; q < 8; q++) {
            ulonglong2 hv = hp[q];
            asm("fma.rn.f32x2 %0, %1, %2, %0;" : "+l"(acc[2 * q])     : "l"(hv.x), "l"(w2));
            asm("fma.rn.f32x2 %0, %1, %2, %0;" : "+l"(acc[2 * q + 1]) : "l"(hv.y), "l"(w2));
        }
    }
    __syncthreads();          // everyone done reading hTs
    float* y1s = hTs;         // reuse as [n][j]
#pragma unroll
    for (int p = 0; p < 16; p++) {
        float lo, hi;
        asm("mov.b64 {%0,%1}, %2;" : "=f"(lo), "=f"(hi) : "l"(acc[p]));
        int n0 = half * 32 + 2 * p;
        y1s[n0 * HID_D + j]       = fmaxf(lo, 0.f);
        y1s[(n0 + 1) * HID_D + j] = fmaxf(hi, 0.f);
    }
    __syncthreads();

    // layer 2: 64 nodes x 12 outputs
    for (int o = tid; o < MLP_NPB * OUT_D; o += 256) {
        int n = o / OUT_D, oo = o - n * OUT_D;
        int gn = base + n;
        if (gn < N_NODES) {
            float s = b2s[oo];
            const float* yr = y1s + n * HID_D;
#pragma unroll 16
            for (int jj = 0; jj < HID_D; jj++) s = fmaf(yr[jj], W2s[jj * OUT_D + oo], s);
            out_y[gn * OUT_D + oo] = s;
        }
    }
}

// ---------------- launch ----------------
extern "C" void kernel_launch(void* const* d_in, const int* in_sizes, int n_in,
                              void* d_out, int out_size) {
    (void)in_sizes; (void)n_in;
    const float* x = (const float*)d_in[0];
    // d_in[1] = full-graph edge_index: provably unused by the reference
    RegPtrs rp;
    for (int r = 0; r < NREG; r++) {
        rp.idx[r] = (const int*)d_in[2 + r];
        rp.w[r]   = (const float*)d_in[7 + r];
    }
    const float* Wc_z = (const float*)d_in[12];
    const float* bc_z = (const float*)d_in[13];
    const float* Wl_z = (const float*)d_in[14];
    const float* bl_z = (const float*)d_in[15];
    // d_in[16..19] = reset-gate params: cannot influence output (H0 = 0)
    const float* Wc_h = (const float*)d_in[20];
    const float* bc_h = (const float*)d_in[21];
    const float* Wl_h = (const float*)d_in[22];
    const float* bl_h = (const float*)d_in[23];
    const float* att  = (const float*)d_in[24];
    const float* W1   = (const float*)d_in[25];
    const float* b1   = (const float*)d_in[26];
    const float* W2   = (const float*)d_in[27];
    const float* b2   = (const float*)d_in[28];

    float* out   = (float*)d_out;
    float* out_y = out;
    int write_h  = (out_size >= N_NODES * (OUT_D + C_DIM)) ? 1 : 0;
    float* out_h = out + N_NODES * OUT_D;

    k_precompute<<<1, 256>>>(Wc_z, bc_z, Wl_z, bl_z, Wc_h, bc_h, Wl_h, bl_h, att);
    k_init_deg<<<(NREG * N_NODES + 255) / 256, 256>>>();
    dim3 gdeg((ER_E + 255) / 256, NREG);
    k_deg<<<gdeg, 256>>>(rp);
    k_dinv<<<(N_NODES + 255) / 256, 256>>>();
    k_ax_self<<<(N_NODES * FT + 255) / 256, 256>>>(x);
    dim3 gsc((ER_E + 7) / 8, NREG);   // 8 warps/block, 1 warp per edge
    k_scatter<<<gsc, 256>>>(rp, x);

    cudaFuncSetAttribute(k_gate, cudaFuncAttributeMaxDynamicSharedMemorySize, GATE_SMEMB);
    k_gate<<<N_NODES / GATE_NPB, 256, GATE_SMEMB>>>(out_h, write_h);

    cudaFuncSetAttribute(k_mlp, cudaFuncAttributeMaxDynamicSharedMemorySize, MLP_SMEMB);
    k_mlp<<<(N_NODES + MLP_NPB - 1) / MLP_NPB, 256, MLP_SMEMB>>>(W1, b1, W2, b2, out_y);
}

// round 5
// speedup vs baseline: 1.5114x; 1.5114x over previous
#include <cuda_runtime.h>

#define N_NODES 20000
#define F_DIM   4
#define T_DIM   12
#define C_DIM   256
#define FT      48          // F*T
#define ER_E    30000
#define HID_D   128
#define OUT_D   12
#define NREG    5

// ---------------- device scratch (no allocations allowed) ----------------
__device__ float g_dinv[NREG * N_NODES];     // deg -> rsqrt(deg) in place
__device__ float g_selfc[N_NODES];           // sum_r 1/deg_r
__device__ float g_Xp[N_NODES * FT];         // x permuted to [n][t*4+f]
__device__ float g_AX[N_NODES * FT];         // aggregated x, layout [n][t*4+f]
__device__ float g_Mzh[F_DIM * C_DIM * 2];   // interleaved (mz, mh) per (f,c)
__device__ float g_bzh[C_DIM * 2];           // interleaved (bz, bh)
__device__ float g_probs[T_DIM];
__device__ float g_hreluT[C_DIM * N_NODES];  // relu(h), TRANSPOSED [c][n]

struct RegPtrs { const int* idx[NREG]; const float* w[NREG]; };

// ---------------- 1: zero AX/M/b, init deg, permute x ----------------
__global__ void k_zero_perm(const float* __restrict__ x) {
    int i = blockIdx.x * blockDim.x + threadIdx.x;
    if (i < N_NODES * FT) {
        int n = i / FT;
        int e = i - n * FT;          // e = f*12 + t
        int f = e / T_DIM;
        int t = e - f * T_DIM;
        g_Xp[n * FT + t * 4 + f] = x[i];
        g_AX[i] = 0.f;
    }
    if (i < NREG * N_NODES) g_dinv[i] = 1.0f;     // self-loop contributes 1
    if (i < F_DIM * C_DIM * 2) g_Mzh[i] = 0.f;
    if (i < C_DIM * 2) g_bzh[i] = 0.f;
}

// ---------------- 2: weighted in-degree ----------------
__global__ void k_deg(RegPtrs rp) {
    int e = blockIdx.x * blockDim.x + threadIdx.x;
    int r = blockIdx.y;
    if (e < ER_E) {
        int dst = rp.idx[r][ER_E + e];
        atomicAdd(&g_dinv[r * N_NODES + dst], rp.w[r][e]);
    }
}

// ---------------- 3: deg -> rsqrt, self coefficient ----------------
__global__ void k_dinv() {
    int i = blockIdx.x * blockDim.x + threadIdx.x;
    if (i < N_NODES) {
        float s = 0.f;
#pragma unroll
        for (int r = 0; r < NREG; r++) {
            float d = g_dinv[r * N_NODES + i];
            g_dinv[r * N_NODES + i] = rsqrtf(d);
            s += __fdividef(1.0f, d);
        }
        g_selfc[i] = s;
    }
}

// ---------------- 4 (PROFILED SLOT): edge scatter with v4 reductions ----------------
// 4 lanes per edge; each lane does 3 x red.global.add.v4.f32 (48 floats/edge)
__global__ void k_scatter(RegPtrs rp) {
    int lane = threadIdx.x & 31;
    int warp = threadIdx.x >> 5;                       // 0..7
    int r = blockIdx.y;
    int e = (blockIdx.x * 8 + warp) * 8 + (lane >> 2);
    int part = lane & 3;
    if (e >= ER_E) return;
    const int* idx = rp.idx[r];
    int src = idx[e];
    int dst = idx[ER_E + e];
    float coef = g_dinv[r * N_NODES + src] * rp.w[r][e] * g_dinv[r * N_NODES + dst];
    const float4* xs = (const float4*)(g_Xp + (size_t)src * FT) + part * 3;
    float4* ax = (float4*)(g_AX + (size_t)dst * FT) + part * 3;
#pragma unroll
    for (int q = 0; q < 3; q++) {
        float4 v = xs[q];
        asm volatile("red.global.add.v4.f32 [%0], {%1, %2, %3, %4};"
                     :: "l"(ax + q), "f"(coef * v.x), "f"(coef * v.y),
                        "f"(coef * v.z), "f"(coef * v.w) : "memory");
    }
}

// ---------------- 5: add self-loop term (vectorized) ----------------
__global__ void k_self_add() {
    int i = blockIdx.x * blockDim.x + threadIdx.x;    // over float4s
    if (i < N_NODES * FT / 4) {
        int n = i / (FT / 4);
        float s = g_selfc[n];
        float4 v = ((const float4*)g_Xp)[i];
        float4 a = ((float4*)g_AX)[i];
        a.x = fmaf(s, v.x, a.x); a.y = fmaf(s, v.y, a.y);
        a.z = fmaf(s, v.z, a.z); a.w = fmaf(s, v.w, a.w);
        ((float4*)g_AX)[i] = a;
    }
}

// ---------------- 6: fold Wc@Wl[:C] + biases (16 blocks), softmax ----------------
__global__ void k_precompute(const float* __restrict__ Wc_z, const float* __restrict__ bc_z,
                             const float* __restrict__ Wl_z, const float* __restrict__ bl_z,
                             const float* __restrict__ Wc_h, const float* __restrict__ bc_h,
                             const float* __restrict__ Wl_h, const float* __restrict__ bl_h,
                             const float* __restrict__ attention) {
    __shared__ float sWcz[F_DIM * 16], sWch[F_DIM * 16];  // only this block's k-slice
    __shared__ float sbcz[16], sbch[16];
    int tid = threadIdx.x;  // 256 threads = one channel each
    int b = blockIdx.x;     // 16 blocks, k-slice [b*16, b*16+16)
    int k0 = b * 16;
    if (tid < F_DIM * 16) {
        int f = tid >> 4, kk = tid & 15;
        sWcz[tid] = Wc_z[f * C_DIM + k0 + kk];
        sWch[tid] = Wc_h[f * C_DIM + k0 + kk];
    }
    if (tid < 16) { sbcz[tid] = bc_z[k0 + tid]; sbch[tid] = bc_h[k0 + tid]; }
    __syncthreads();
    float mz[F_DIM] = {0, 0, 0, 0}, mh[F_DIM] = {0, 0, 0, 0}, bz = 0.f, bh = 0.f;
#pragma unroll 4
    for (int kk = 0; kk < 16; kk++) {
        int k = k0 + kk;
        float wz = Wl_z[k * C_DIM + tid];
        float wh = Wl_h[k * C_DIM + tid];
#pragma unroll
        for (int f = 0; f < F_DIM; f++) {
            mz[f] = fmaf(sWcz[f * 16 + kk], wz, mz[f]);
            mh[f] = fmaf(sWch[f * 16 + kk], wh, mh[f]);
        }
        bz = fmaf(sbcz[kk], wz, bz);
        bh = fmaf(sbch[kk], wh, bh);
    }
#pragma unroll
    for (int f = 0; f < F_DIM; f++) {
        atomicAdd(&g_Mzh[(f * C_DIM + tid) * 2],     mz[f]);
        atomicAdd(&g_Mzh[(f * C_DIM + tid) * 2 + 1], mh[f]);
    }
    if (b == 0) { bz += bl_z[tid]; bh += bl_h[tid]; }
    atomicAdd(&g_bzh[tid * 2],     bz);
    atomicAdd(&g_bzh[tid * 2 + 1], bh);
    if (b == 0 && tid == 0) {
        float mx = -1e30f;
        for (int t = 0; t < T_DIM; t++) mx = fmaxf(mx, attention[t]);
        float p[T_DIM], s = 0.f;
        for (int t = 0; t < T_DIM; t++) { p[t] = __expf(attention[t] - mx); s += p[t]; }
        float is = __fdividef(1.0f, s);
        for (int t = 0; t < T_DIM; t++) g_probs[t] = p[t] * is;
    }
}

// ---------------- 7: gate kernel (packed f32x2 dot products) ----------------
// smem floats: Mzh 2048 | bzh 512 | AXd 3072 (duplicated pairs) | hs 32*257=8224
#define GATE_NPB   32
#define GATE_SMEMF (2048 + 512 + 3072 + 32 * 257)
#define GATE_SMEMB (GATE_SMEMF * 4)

__global__ void __launch_bounds__(256, 4)
k_gate(float* __restrict__ out_h, int write_h) {
    extern __shared__ float sm[];
    float* Mzs = sm;                 // 2048 (interleaved mz,mh)
    float* bzs = Mzs + 2048;         // 512
    float* AXd = bzs + 512;          // 3072: [n][t*4+f] with each value duplicated
    float* hs  = AXd + 3072;         // 32 * 257 (padded for transpose)

    int tid = threadIdx.x;
    for (int i = tid; i < 2048; i += 256) Mzs[i] = g_Mzh[i];
    bzs[tid] = g_bzh[tid];
    bzs[256 + tid] = g_bzh[256 + tid];
    int base = blockIdx.x * GATE_NPB;
    for (int i = tid; i < GATE_NPB * FT; i += 256) {
        float v = g_AX[base * FT + i];
        ((float2*)AXd)[i] = make_float2(v, v);
    }
    __syncthreads();

    float pr[T_DIM];
#pragma unroll
    for (int t = 0; t < T_DIM; t++) pr[t] = g_probs[t];

    int c = tid;
    const unsigned long long* M64 = (const unsigned long long*)Mzs;
    unsigned long long mm0 = M64[c], mm1 = M64[256 + c], mm2 = M64[512 + c], mm3 = M64[768 + c];
    unsigned long long bb = ((const unsigned long long*)bzs)[c];

    for (int ln = 0; ln < GATE_NPB; ln++) {
        const ulonglong2* axp = (const ulonglong2*)(AXd + ln * 96);
        float acc = 0.f;
#pragma unroll
        for (int t = 0; t < T_DIM; t++) {
            ulonglong2 a01 = axp[2 * t];
            ulonglong2 a23 = axp[2 * t + 1];
            unsigned long long d = bb;
            asm("fma.rn.f32x2 %0, %1, %2, %0;" : "+l"(d) : "l"(a01.x), "l"(mm0));
            asm("fma.rn.f32x2 %0, %1, %2, %0;" : "+l"(d) : "l"(a01.y), "l"(mm1));
            asm("fma.rn.f32x2 %0, %1, %2, %0;" : "+l"(d) : "l"(a23.x), "l"(mm2));
            asm("fma.rn.f32x2 %0, %1, %2, %0;" : "+l"(d) : "l"(a23.y), "l"(mm3));
            float az, ah;
            asm("mov.b64 {%0, %1}, %2;" : "=f"(az), "=f"(ah) : "l"(d));
            // (1-sigmoid(az))*tanh(ah) = (e2-1) / ((1+ez)*(e2+1)), e2=e^{2ah}, ez=e^{az}
            float ez   = __expf(az);
            float e2   = __expf(fminf(ah, 44.0f) * 2.0f);  // den=inf -> val=0 (correct limit)
            float e2p1 = e2 + 1.0f;
            float den  = fmaf(ez, e2p1, e2p1);
            acc = fmaf(pr[t], __fdividef(e2 - 1.0f, den), acc);
        }
        if (write_h) out_h[(base + ln) * C_DIM + c] = acc;   // raw h output
        hs[ln * 257 + c] = fmaxf(acc, 0.f);
    }
    __syncthreads();

    // transposed relu'd write: g_hreluT[c][n]
    for (int idx = tid; idx < GATE_NPB * C_DIM; idx += 256) {
        int cc = idx >> 5, n = idx & 31;
        g_hreluT[cc * N_NODES + base + n] = hs[n * 257 + cc];
    }
}

// ---------------- 8: MLP kernel: relu(h) @ W1 -> relu -> @ W2 ----------------
// smem floats: hTs 16384 (reused as y1s) | b1 128 | b2 16 | W2 1536 = 18064
#define MLP_NPB   64
#define MLP_SMEMF (16384 + 128 + 16 + 1536)
#define MLP_SMEMB (MLP_SMEMF * 4)

__global__ void __launch_bounds__(256, 3)
k_mlp(const float* __restrict__ W1, const float* __restrict__ b1,
      const float* __restrict__ W2, const float* __restrict__ b2,
      float* __restrict__ out_y) {
    extern __shared__ float sm[];
    float* hTs = sm;                  // 16384  [k][n]  (aliased to y1s after sync)
    float* b1s = hTs + 16384;         // 128
    float* b2s = b1s + 128;           // 16
    float* W2s = b2s + 16;            // 1536

    int tid = threadIdx.x;
    int base = blockIdx.x * MLP_NPB;

    for (int i = tid; i < 1536; i += 256) W2s[i] = W2[i];
    if (tid < HID_D) b1s[tid] = b1[tid];
    if (tid < 16) b2s[tid] = (tid < OUT_D) ? b2[tid] : 0.f;
    for (int i = tid; i < C_DIM * MLP_NPB; i += 256) {
        int k = i >> 6, n = i & 63;
        int gn = base + n;
        hTs[i] = (gn < N_NODES) ? g_hreluT[k * N_NODES + gn] : 0.f;
    }
    __syncthreads();

    // layer 1, packed-fp32 pipe: thread (j, half) covers 32 nodes = 16 f32x2 pairs
    int j = tid & 127;
    int half = tid >> 7;
    unsigned long long acc[16];
    {
        float bj = b1s[j];
        unsigned long long binit;
        asm("mov.b64 %0, {%1, %1};" : "=l"(binit) : "f"(bj));
#pragma unroll
        for (int p = 0; p < 16; p++) acc[p] = binit;
    }
    const float* hbase = hTs + half * 32;
#pragma unroll 4
    for (int k = 0; k < C_DIM; k++) {
        float w = W1[k * HID_D + j];                 // L2-resident, coalesced
        unsigned long long w2;
        asm("mov.b64 %0, {%1, %1};" : "=l"(w2) : "f"(w));
        const ulonglong2* hp = (const ulonglong2*)(hbase + k * MLP_NPB);
#pragma unroll
        for (int q = 0; q < 8; q++) {
            ulonglong2 hv = hp[q];
            asm("fma.rn.f32x2 %0, %1, %2, %0;" : "+l"(acc[2 * q])     : "l"(hv.x), "l"(w2));
            asm("fma.rn.f32x2 %0, %1, %2, %0;" : "+l"(acc[2 * q + 1]) : "l"(hv.y), "l"(w2));
        }
    }
    __syncthreads();          // everyone done reading hTs
    float* y1s = hTs;         // reuse as [n][j]
#pragma unroll
    for (int p = 0; p < 16; p++) {
        float lo, hi;
        asm("mov.b64 {%0, %1}, %2;" : "=f"(lo), "=f"(hi) : "l"(acc[p]));
        int n0 = half * 32 + 2 * p;
        y1s[n0 * HID_D + j]       = fmaxf(lo, 0.f);
        y1s[(n0 + 1) * HID_D + j] = fmaxf(hi, 0.f);
    }
    __syncthreads();

    // layer 2: 64 nodes x 12 outputs
    for (int o = tid; o < MLP_NPB * OUT_D; o += 256) {
        int n = o / OUT_D, oo = o - n * OUT_D;
        int gn = base + n;
        if (gn < N_NODES) {
            float s = b2s[oo];
            const float* yr = y1s + n * HID_D;
#pragma unroll 16
            for (int jj = 0; jj < HID_D; jj++) s = fmaf(yr[jj], W2s[jj * OUT_D + oo], s);
            out_y[gn * OUT_D + oo] = s;
        }
    }
}

// ---------------- launch ----------------
extern "C" void kernel_launch(void* const* d_in, const int* in_sizes, int n_in,
                              void* d_out, int out_size) {
    (void)in_sizes; (void)n_in;
    const float* x = (const float*)d_in[0];
    // d_in[1] = full-graph edge_index: provably unused by the reference
    RegPtrs rp;
    for (int r = 0; r < NREG; r++) {
        rp.idx[r] = (const int*)d_in[2 + r];
        rp.w[r]   = (const float*)d_in[7 + r];
    }
    const float* Wc_z = (const float*)d_in[12];
    const float* bc_z = (const float*)d_in[13];
    const float* Wl_z = (const float*)d_in[14];
    const float* bl_z = (const float*)d_in[15];
    // d_in[16..19] = reset-gate params: cannot influence output (H0 = 0)
    const float* Wc_h = (const float*)d_in[20];
    const float* bc_h = (const float*)d_in[21];
    const float* Wl_h = (const float*)d_in[22];
    const float* bl_h = (const float*)d_in[23];
    const float* att  = (const float*)d_in[24];
    const float* W1   = (const float*)d_in[25];
    const float* b1   = (const float*)d_in[26];
    const float* W2   = (const float*)d_in[27];
    const float* b2   = (const float*)d_in[28];

    float* out   = (float*)d_out;
    float* out_y = out;
    int write_h  = (out_size >= N_NODES * (OUT_D + C_DIM)) ? 1 : 0;
    float* out_h = out + N_NODES * OUT_D;

    k_zero_perm<<<(N_NODES * FT + 255) / 256, 256>>>(x);                 // 1
    dim3 gdeg((ER_E + 255) / 256, NREG);
    k_deg<<<gdeg, 256>>>(rp);                                            // 2
    k_dinv<<<(N_NODES + 255) / 256, 256>>>();                            // 3
    dim3 gsc((ER_E + 63) / 64, NREG);   // 64 edges/block, 4 lanes/edge
    k_scatter<<<gsc, 256>>>(rp);                                         // 4 <- profiled
    k_self_add<<<(N_NODES * FT / 4 + 255) / 256, 256>>>();               // 5
    k_precompute<<<16, 256>>>(Wc_z, bc_z, Wl_z, bl_z, Wc_h, bc_h, Wl_h, bl_h, att); // 6

    cudaFuncSetAttribute(k_gate, cudaFuncAttributeMaxDynamicSharedMemorySize, GATE_SMEMB);
    k_gate<<<N_NODES / GATE_NPB, 256, GATE_SMEMB>>>(out_h, write_h);     // 7

    cudaFuncSetAttribute(k_mlp, cudaFuncAttributeMaxDynamicSharedMemorySize, MLP_SMEMB);
    k_mlp<<<(N_NODES + MLP_NPB - 1) / MLP_NPB, 256, MLP_SMEMB>>>(W1, b1, W2, b2, out_y); // 8
}

// round 6
// speedup vs baseline: 1.5281x; 1.0111x over previous
#include <cuda_runtime.h>

#define N_NODES 20000
#define F_DIM   4
#define T_DIM   12
#define C_DIM   256
#define FT      48          // F*T
#define ER_E    30000
#define HID_D   128
#define OUT_D   12
#define NREG    5

// ---------------- device scratch (no allocations allowed) ----------------
__device__ float g_dinv[NREG * N_NODES];     // deg -> rsqrt(deg) in place
__device__ float g_selfc[N_NODES];           // sum_r 1/deg_r
__device__ float g_Xp[N_NODES * FT];         // x permuted to [n][t*4+f]
__device__ float g_AX[N_NODES * FT];         // aggregated x (edges only), [n][t*4+f]
__device__ float g_Mzh[F_DIM * C_DIM * 2];   // interleaved (mz, mh) per (f,c)
__device__ float g_bzh[C_DIM * 2];           // interleaved (bz, bh)
__device__ float g_probs[T_DIM];
__device__ float g_hreluT[C_DIM * N_NODES];  // relu(h), TRANSPOSED [c][n]

struct RegPtrs { const int* idx[NREG]; const float* w[NREG]; };

// ---------------- 1: zero AX/M/b, init deg, permute x ----------------
__global__ void k_zero_perm(const float* __restrict__ x) {
    int i = blockIdx.x * blockDim.x + threadIdx.x;
    if (i < N_NODES * FT) {
        int n = i / FT;
        int e = i - n * FT;          // e = f*12 + t
        int f = e / T_DIM;
        int t = e - f * T_DIM;
        g_Xp[n * FT + t * 4 + f] = x[i];
        g_AX[i] = 0.f;
    }
    if (i < NREG * N_NODES) g_dinv[i] = 1.0f;     // self-loop contributes 1
    if (i < F_DIM * C_DIM * 2) g_Mzh[i] = 0.f;
    if (i < C_DIM * 2) g_bzh[i] = 0.f;
}

// ---------------- 2: weighted in-degree ----------------
__global__ void k_deg(RegPtrs rp) {
    int e = blockIdx.x * blockDim.x + threadIdx.x;
    int r = blockIdx.y;
    if (e < ER_E) {
        int dst = rp.idx[r][ER_E + e];
        atomicAdd(&g_dinv[r * N_NODES + dst], rp.w[r][e]);
    }
}

// ---------------- 3: fused dinv (blocks 0..78) + weight-fold (blocks 79..94) ----------------
#define DINV_BLOCKS 79
__global__ void k_dinv_precomp(const float* __restrict__ Wc_z, const float* __restrict__ bc_z,
                               const float* __restrict__ Wl_z, const float* __restrict__ bl_z,
                               const float* __restrict__ Wc_h, const float* __restrict__ bc_h,
                               const float* __restrict__ Wl_h, const float* __restrict__ bl_h,
                               const float* __restrict__ attention) {
    int tid = threadIdx.x;
    if (blockIdx.x < DINV_BLOCKS) {
        int i = blockIdx.x * 256 + tid;
        if (i < N_NODES) {
            float s = 0.f;
#pragma unroll
            for (int r = 0; r < NREG; r++) {
                float d = g_dinv[r * N_NODES + i];
                g_dinv[r * N_NODES + i] = rsqrtf(d);
                s += __fdividef(1.0f, d);
            }
            g_selfc[i] = s;
        }
        return;
    }
    // ---- weight fold: M = Wc@Wl[:C], b' = bc@Wl[:C] + bl; 16 blocks, k-slice each ----
    __shared__ float sWcz[F_DIM * 16], sWch[F_DIM * 16];
    __shared__ float sbcz[16], sbch[16];
    int b = blockIdx.x - DINV_BLOCKS;   // 0..15
    int k0 = b * 16;
    if (tid < F_DIM * 16) {
        int f = tid >> 4, kk = tid & 15;
        sWcz[tid] = Wc_z[f * C_DIM + k0 + kk];
        sWch[tid] = Wc_h[f * C_DIM + k0 + kk];
    }
    if (tid < 16) { sbcz[tid] = bc_z[k0 + tid]; sbch[tid] = bc_h[k0 + tid]; }
    __syncthreads();
    float mz[F_DIM] = {0, 0, 0, 0}, mh[F_DIM] = {0, 0, 0, 0}, bz = 0.f, bh = 0.f;
#pragma unroll 4
    for (int kk = 0; kk < 16; kk++) {
        int k = k0 + kk;
        float wz = Wl_z[k * C_DIM + tid];
        float wh = Wl_h[k * C_DIM + tid];
#pragma unroll
        for (int f = 0; f < F_DIM; f++) {
            mz[f] = fmaf(sWcz[f * 16 + kk], wz, mz[f]);
            mh[f] = fmaf(sWch[f * 16 + kk], wh, mh[f]);
        }
        bz = fmaf(sbcz[kk], wz, bz);
        bh = fmaf(sbch[kk], wh, bh);
    }
#pragma unroll
    for (int f = 0; f < F_DIM; f++) {
        atomicAdd(&g_Mzh[(f * C_DIM + tid) * 2],     mz[f]);
        atomicAdd(&g_Mzh[(f * C_DIM + tid) * 2 + 1], mh[f]);
    }
    if (b == 0) { bz += bl_z[tid]; bh += bl_h[tid]; }
    atomicAdd(&g_bzh[tid * 2],     bz);
    atomicAdd(&g_bzh[tid * 2 + 1], bh);
    if (b == 0 && tid == 0) {
        float mx = -1e30f;
        for (int t = 0; t < T_DIM; t++) mx = fmaxf(mx, attention[t]);
        float p[T_DIM], s = 0.f;
        for (int t = 0; t < T_DIM; t++) { p[t] = __expf(attention[t] - mx); s += p[t]; }
        float is = __fdividef(1.0f, s);
        for (int t = 0; t < T_DIM; t++) g_probs[t] = p[t] * is;
    }
}

// ---------------- 4 (PROFILED SLOT): edge scatter with v4 reductions ----------------
// 4 lanes per edge; each lane does 3 x red.global.add.v4.f32 (48 floats/edge)
__global__ void k_scatter(RegPtrs rp) {
    int lane = threadIdx.x & 31;
    int warp = threadIdx.x >> 5;                       // 0..7
    int r = blockIdx.y;
    int e = (blockIdx.x * 8 + warp) * 8 + (lane >> 2);
    int part = lane & 3;
    if (e >= ER_E) return;
    const int* idx = rp.idx[r];
    int src = idx[e];
    int dst = idx[ER_E + e];
    float coef = g_dinv[r * N_NODES + src] * rp.w[r][e] * g_dinv[r * N_NODES + dst];
    const float4* xs = (const float4*)(g_Xp + (size_t)src * FT) + part * 3;
    float4* ax = (float4*)(g_AX + (size_t)dst * FT) + part * 3;
#pragma unroll
    for (int q = 0; q < 3; q++) {
        float4 v = xs[q];
        asm volatile("red.global.add.v4.f32 [%0], {%1, %2, %3, %4};"
                     :: "l"(ax + q), "f"(coef * v.x), "f"(coef * v.y),
                        "f"(coef * v.z), "f"(coef * v.w) : "memory");
    }
}

// ---------------- 5: gate kernel (f32x2 dot + batched-fraction transcendentals) ----------------
// smem floats: Mzh 2048 | bzh 512 | AXd 3072 (duplicated pairs) | hs 32*257=8224
#define GATE_NPB   32
#define GATE_SMEMF (2048 + 512 + 3072 + 32 * 257)
#define GATE_SMEMB (GATE_SMEMF * 4)

__global__ void __launch_bounds__(256, 4)
k_gate(float* __restrict__ out_h, int write_h) {
    extern __shared__ float sm[];
    float* Mzs = sm;                 // 2048 (interleaved mz,mh)
    float* bzs = Mzs + 2048;         // 512
    float* AXd = bzs + 512;          // 3072: [n][t*4+f], each value duplicated
    float* hs  = AXd + 3072;         // 32 * 257 (padded for transpose)

    int tid = threadIdx.x;
    for (int i = tid; i < 2048; i += 256) Mzs[i] = g_Mzh[i];
    bzs[tid] = g_bzh[tid];
    bzs[256 + tid] = g_bzh[256 + tid];
    int base = blockIdx.x * GATE_NPB;
    // fused self-loop: AX_total = AX_edges + selfc[n] * Xp
    for (int i = tid; i < GATE_NPB * FT; i += 256) {
        int n = base + i / FT;
        float v = fmaf(g_selfc[n], g_Xp[base * FT + i], g_AX[base * FT + i]);
        ((float2*)AXd)[i] = make_float2(v, v);
    }
    __syncthreads();

    float pr[T_DIM];
#pragma unroll
    for (int t = 0; t < T_DIM; t++) pr[t] = g_probs[t];

    int c = tid;
    const unsigned long long* M64 = (const unsigned long long*)Mzs;
    unsigned long long mm0 = M64[c], mm1 = M64[256 + c], mm2 = M64[512 + c], mm3 = M64[768 + c];
    unsigned long long bb = ((const unsigned long long*)bzs)[c];

    for (int ln = 0; ln < GATE_NPB; ln++) {
        const ulonglong2* axp = (const ulonglong2*)(AXd + ln * 96);
        float Nacc = 0.f, Dacc = 1.f;
#pragma unroll
        for (int t = 0; t < T_DIM; t++) {
            ulonglong2 a01 = axp[2 * t];
            ulonglong2 a23 = axp[2 * t + 1];
            unsigned long long d = bb;
            asm("fma.rn.f32x2 %0, %1, %2, %0;" : "+l"(d) : "l"(a01.x), "l"(mm0));
            asm("fma.rn.f32x2 %0, %1, %2, %0;" : "+l"(d) : "l"(a01.y), "l"(mm1));
            asm("fma.rn.f32x2 %0, %1, %2, %0;" : "+l"(d) : "l"(a23.x), "l"(mm2));
            asm("fma.rn.f32x2 %0, %1, %2, %0;" : "+l"(d) : "l"(a23.y), "l"(mm3));
            float az, ah;
            asm("mov.b64 {%0, %1}, %2;" : "=f"(az), "=f"(ah) : "l"(d));
            // stable form, denominators in [1,4]:
            //   (1-sigmoid(az)) = (az>=0 ? em : 1)/(1+em),   em  = e^{-|az|}
            //   tanh(ah)        = copysign(1-em2, ah)/(1+em2), em2 = e^{-2|ah|}
            float em  = __expf(-fabsf(az));
            float em2 = __expf(-2.0f * fabsf(ah));
            float ns  = (az >= 0.f) ? em : 1.0f;
            float n_t = ns * copysignf(1.0f - em2, ah) * pr[t];
            float d_t = (1.0f + em) * (1.0f + em2);
            // running fraction: N/D = sum_{<=t} n/d ;  D <= 4^12, never overflows
            Nacc = fmaf(Nacc, d_t, n_t * Dacc);
            Dacc *= d_t;
        }
        float acc = __fdividef(Nacc, Dacc);          // ONE division per (node,channel)
        if (write_h) out_h[(base + ln) * C_DIM + c] = acc;   // raw h output
        hs[ln * 257 + c] = fmaxf(acc, 0.f);
    }
    __syncthreads();

    // transposed relu'd write: g_hreluT[c][n]
    for (int idx = tid; idx < GATE_NPB * C_DIM; idx += 256) {
        int cc = idx >> 5, n = idx & 31;
        g_hreluT[cc * N_NODES + base + n] = hs[n * 257 + cc];
    }
}

// ---------------- 6: MLP kernel: relu(h) @ W1 -> relu -> @ W2 ----------------
// smem floats: hTs 16384 (reused as y1s) | b1 128 | b2 16 | W2 1536 = 18064
#define MLP_NPB   64
#define MLP_SMEMF (16384 + 128 + 16 + 1536)
#define MLP_SMEMB (MLP_SMEMF * 4)

__global__ void __launch_bounds__(256, 3)
k_mlp(const float* __restrict__ W1, const float* __restrict__ b1,
      const float* __restrict__ W2, const float* __restrict__ b2,
      float* __restrict__ out_y) {
    extern __shared__ float sm[];
    float* hTs = sm;                  // 16384  [k][n]  (aliased to y1s after sync)
    float* b1s = hTs + 16384;         // 128
    float* b2s = b1s + 128;           // 16
    float* W2s = b2s + 16;            // 1536

    int tid = threadIdx.x;
    int base = blockIdx.x * MLP_NPB;

    for (int i = tid; i < 1536; i += 256) W2s[i] = W2[i];
    if (tid < HID_D) b1s[tid] = b1[tid];
    if (tid < 16) b2s[tid] = (tid < OUT_D) ? b2[tid] : 0.f;
    for (int i = tid; i < C_DIM * MLP_NPB; i += 256) {
        int k = i >> 6, n = i & 63;
        int gn = base + n;
        hTs[i] = (gn < N_NODES) ? g_hreluT[k * N_NODES + gn] : 0.f;
    }
    __syncthreads();

    // layer 1, packed-fp32 pipe: thread (j, half) covers 32 nodes = 16 f32x2 pairs
    int j = tid & 127;
    int half = tid >> 7;
    unsigned long long acc[16];
    {
        float bj = b1s[j];
        unsigned long long binit;
        asm("mov.b64 %0, {%1, %1};" : "=l"(binit) : "f"(bj));
#pragma unroll
        for (int p = 0; p < 16; p++) acc[p] = binit;
    }
    const float* hbase = hTs + half * 32;
#pragma unroll 1
    for (int k0 = 0; k0 < C_DIM; k0 += 8) {
        float wreg[8];                               // 8-wide prefetch (MLP=8)
#pragma unroll
        for (int kk = 0; kk < 8; kk++) wreg[kk] = W1[(k0 + kk) * HID_D + j];
#pragma unroll
        for (int kk = 0; kk < 8; kk++) {
            unsigned long long w2;
            asm("mov.b64 %0, {%1, %1};" : "=l"(w2) : "f"(wreg[kk]));
            const ulonglong2* hp = (const ulonglong2*)(hbase + (k0 + kk) * MLP_NPB);
#pragma unroll
            for (int q = 0; q < 8; q++) {
                ulonglong2 hv = hp[q];
                asm("fma.rn.f32x2 %0, %1, %2, %0;" : "+l"(acc[2 * q])     : "l"(hv.x), "l"(w2));
                asm("fma.rn.f32x2 %0, %1, %2, %0;" : "+l"(acc[2 * q + 1]) : "l"(hv.y), "l"(w2));
            }
        }
    }
    __syncthreads();          // everyone done reading hTs
    float* y1s = hTs;         // reuse as [n][j]
#pragma unroll
    for (int p = 0; p < 16; p++) {
        float lo, hi;
        asm("mov.b64 {%0, %1}, %2;" : "=f"(lo), "=f"(hi) : "l"(acc[p]));
        int n0 = half * 32 + 2 * p;
        y1s[n0 * HID_D + j]       = fmaxf(lo, 0.f);
        y1s[(n0 + 1) * HID_D + j] = fmaxf(hi, 0.f);
    }
    __syncthreads();

    // layer 2: 64 nodes x 12 outputs
    for (int o = tid; o < MLP_NPB * OUT_D; o += 256) {
        int n = o / OUT_D, oo = o - n * OUT_D;
        int gn = base + n;
        if (gn < N_NODES) {
            float s = b2s[oo];
            const float* yr = y1s + n * HID_D;
#pragma unroll 16
            for (int jj = 0; jj < HID_D; jj++) s = fmaf(yr[jj], W2s[jj * OUT_D + oo], s);
            out_y[gn * OUT_D + oo] = s;
        }
    }
}

// ---------------- launch ----------------
extern "C" void kernel_launch(void* const* d_in, const int* in_sizes, int n_in,
                              void* d_out, int out_size) {
    (void)in_sizes; (void)n_in;
    const float* x = (const float*)d_in[0];
    // d_in[1] = full-graph edge_index: provably unused by the reference
    RegPtrs rp;
    for (int r = 0; r < NREG; r++) {
        rp.idx[r] = (const int*)d_in[2 + r];
        rp.w[r]   = (const float*)d_in[7 + r];
    }
    const float* Wc_z = (const float*)d_in[12];
    const float* bc_z = (const float*)d_in[13];
    const float* Wl_z = (const float*)d_in[14];
    const float* bl_z = (const float*)d_in[15];
    // d_in[16..19] = reset-gate params: cannot influence output (H0 = 0)
    const float* Wc_h = (const float*)d_in[20];
    const float* bc_h = (const float*)d_in[21];
    const float* Wl_h = (const float*)d_in[22];
    const float* bl_h = (const float*)d_in[23];
    const float* att  = (const float*)d_in[24];
    const float* W1   = (const float*)d_in[25];
    const float* b1   = (const float*)d_in[26];
    const float* W2   = (const float*)d_in[27];
    const float* b2   = (const float*)d_in[28];

    float* out   = (float*)d_out;
    float* out_y = out;
    int write_h  = (out_size >= N_NODES * (OUT_D + C_DIM)) ? 1 : 0;
    float* out_h = out + N_NODES * OUT_D;

    k_zero_perm<<<(N_NODES * FT + 255) / 256, 256>>>(x);                 // 1
    dim3 gdeg((ER_E + 255) / 256, NREG);
    k_deg<<<gdeg, 256>>>(rp);                                            // 2
    k_dinv_precomp<<<DINV_BLOCKS + 16, 256>>>(Wc_z, bc_z, Wl_z, bl_z,
                                              Wc_h, bc_h, Wl_h, bl_h, att); // 3
    dim3 gsc((ER_E + 63) / 64, NREG);   // 64 edges/block, 4 lanes/edge
    k_scatter<<<gsc, 256>>>(rp);                                         // 4 <- profiled

    cudaFuncSetAttribute(k_gate, cudaFuncAttributeMaxDynamicSharedMemorySize, GATE_SMEMB);
    k_gate<<<N_NODES / GATE_NPB, 256, GATE_SMEMB>>>(out_h, write_h);     // 5

    cudaFuncSetAttribute(k_mlp, cudaFuncAttributeMaxDynamicSharedMemorySize, MLP_SMEMB);
    k_mlp<<<(N_NODES + MLP_NPB - 1) / MLP_NPB, 256, MLP_SMEMB>>>(W1, b1, W2, b2, out_y); // 6
}